// round 1
// baseline (speedup 1.0000x reference)
#include <cuda_runtime.h>
#include <cstdint>
#include <cstddef>

#define B_        32
#define DIM_      4096
#define HD        128
#define NKV       8
#define NH        32
#define MAXSEQ    4096
#define NEWPOS    4095
#define QKV_ROWS  6144
#define SPLIT_QKV 6
#define SPLIT_O   9
#define ATT_SPLITS 4

typedef unsigned long long ull;

// ---------------- scratch (static __device__, no allocations) ----------------
__device__ float g_part_qkv[SPLIT_QKV * B_ * QKV_ROWS];   // 4.7 MB
__device__ float g_part_o  [SPLIT_O   * B_ * DIM_];       // 4.7 MB
__device__ float g_q   [B_ * NH  * HD];                   // roped, pre-scaled q
__device__ float g_knew[B_ * NKV * HD];                   // new k (roped)
__device__ float g_vnew[B_ * NKV * HD];                   // new v
__device__ float g_attn[B_ * NH * HD];                    // attention output
__device__ float g_pacc[B_ * NKV * ATT_SPLITS * 4 * HD];  // split partial acc
__device__ float g_pm  [B_ * NKV * ATT_SPLITS * 4];
__device__ float g_pl  [B_ * NKV * ATT_SPLITS * 4];

// ---------------- f32x2 packed-FMA helpers (Blackwell) ----------------
__device__ __forceinline__ ull splat2(float x) {
    ull r; unsigned u = __float_as_uint(x);
    asm("mov.b64 %0, {%1, %2};" : "=l"(r) : "r"(u), "r"(u));
    return r;
}
__device__ __forceinline__ ull pack2(float lo, float hi) {
    ull r;
    asm("mov.b64 %0, {%1, %2};" : "=l"(r)
        : "r"(__float_as_uint(lo)), "r"(__float_as_uint(hi)));
    return r;
}
__device__ __forceinline__ void fma2(ull& d, ull a, ull b) {
    asm("fma.rn.f32x2 %0, %1, %2, %3;" : "=l"(d) : "l"(a), "l"(b), "l"(d));
}
__device__ __forceinline__ void unpack2(ull v, float& lo, float& hi) {
    unsigned a, b;
    asm("mov.b64 {%0, %1}, %2;" : "=r"(a), "=r"(b) : "l"(v));
    lo = __uint_as_float(a); hi = __uint_as_float(b);
}

// ---------------- split-K GEMM: C[32, Ntot] = X[32,4096] * W^T ----------------
// W row-major (out_row, 4096). which=0: X=Xp, part=g_part_qkv; which=1: X=g_attn, part=g_part_o.
__global__ __launch_bounds__(256) void gemm_splitk(
    const float* __restrict__ Xp,
    const float* __restrict__ W0, const float* __restrict__ W1, const float* __restrict__ W2,
    int n1, int n2, int Ntot, int nsplit, int which)
{
    __shared__ float Xs[32 * 32];    // [kk][m ^ swz]
    __shared__ float Ws[32 * 128];   // [kk][n ^ swz]

    const float* X   = which ? g_attn    : Xp;
    float*       part = which ? g_part_o : g_part_qkv;

    const int nb = blockIdx.x * 128;
    const int z  = blockIdx.y;
    const int kts = (z * 128) / nsplit;
    const int kte = ((z + 1) * 128) / nsplit;

    const float* W; int roff;
    if (nb < n1)      { W = W0; roff = 0;  }
    else if (nb < n2) { W = W1; roff = n1; }
    else              { W = W2; roff = n2; }

    const int t    = threadIdx.x;
    const int lane = t & 31;
    const int warp = t >> 5;
    const int m0   = warp * 4;     // 8 warps * 4 = 32 rows
    const int n0   = lane * 4;     // 32 lanes * 4 = 128 cols

    // loader mapping
    const int lm  = t >> 3;         // 0..31 (X row / W local row base)
    const int lk4 = (t & 7) * 4;    // k offset in tile
    const float* xrow  = X + (size_t)lm * DIM_;
    const float* wbase = W + (size_t)(nb - roff) * DIM_;

    ull acc[4][2];
#pragma unroll
    for (int i = 0; i < 4; ++i) { acc[i][0] = 0ull; acc[i][1] = 0ull; }

    float4 xp4;
    float4 wp4[4];
    if (kts < kte) {
        int k0 = kts * 32;
        xp4 = *(const float4*)(xrow + k0 + lk4);
#pragma unroll
        for (int j = 0; j < 4; ++j)
            wp4[j] = *(const float4*)(wbase + (size_t)(lm + 32 * j) * DIM_ + k0 + lk4);
    }

    for (int kt = kts; kt < kte; ++kt) {
        __syncthreads();
        // store prefetched tile, XOR-swizzled for conflict-free STS & LDS.128
#pragma unroll
        for (int j = 0; j < 4; ++j) {
            int kk = lk4 + j;
            int sw = ((kk >> 2) & 7) << 2;
            Xs[kk * 32 + (lm ^ sw)] = ((const float*)&xp4)[j];
        }
#pragma unroll
        for (int jj = 0; jj < 4; ++jj) {
#pragma unroll
            for (int j = 0; j < 4; ++j) {
                int kk = lk4 + j;
                int sw = ((kk >> 2) & 7) << 2;
                Ws[kk * 128 + ((lm ^ sw) + 32 * jj)] = ((const float*)&wp4[jj])[j];
            }
        }
        __syncthreads();
        if (kt + 1 < kte) {
            int k0 = (kt + 1) * 32;
            xp4 = *(const float4*)(xrow + k0 + lk4);
#pragma unroll
            for (int j = 0; j < 4; ++j)
                wp4[j] = *(const float4*)(wbase + (size_t)(lm + 32 * j) * DIM_ + k0 + lk4);
        }
#pragma unroll
        for (int kk = 0; kk < 32; ++kk) {
            int sw = ((kk >> 2) & 7) << 2;
            const float4 a4 = *(const float4*)(Xs + kk * 32  + (m0 ^ sw));
            const float4 b4 = *(const float4*)(Ws + kk * 128 + (n0 ^ sw));
            ull B0 = pack2(b4.x, b4.y);
            ull B1 = pack2(b4.z, b4.w);
            ull A;
            A = splat2(a4.x); fma2(acc[0][0], A, B0); fma2(acc[0][1], A, B1);
            A = splat2(a4.y); fma2(acc[1][0], A, B0); fma2(acc[1][1], A, B1);
            A = splat2(a4.z); fma2(acc[2][0], A, B0); fma2(acc[2][1], A, B1);
            A = splat2(a4.w); fma2(acc[3][0], A, B0); fma2(acc[3][1], A, B1);
        }
    }

    const size_t base = (size_t)z * B_ * (size_t)Ntot;
#pragma unroll
    for (int i = 0; i < 4; ++i) {
        float l0, h0, l1, h1;
        unpack2(acc[i][0], l0, h0);
        unpack2(acc[i][1], l1, h1);
        float4 o4 = make_float4(l0, h0, l1, h1);
        *(float4*)(part + base + (size_t)(m0 + i) * Ntot + nb + n0) = o4;
    }
}

// ---------------- combine QKV split-K partials + RoPE ----------------
__global__ void qkv_combine(const float* __restrict__ fc, const float* __restrict__ fs) {
    int p = blockIdx.x * blockDim.x + threadIdx.x;   // pair index, < 32*3072
    if (p >= B_ * (QKV_ROWS / 2)) return;
    int m  = p / (QKV_ROWS / 2);
    int o  = (p % (QKV_ROWS / 2)) * 2;
    float se = 0.f, so = 0.f;
#pragma unroll
    for (int z = 0; z < SPLIT_QKV; ++z) {
        const float* pp = g_part_qkv + ((size_t)z * B_ + m) * QKV_ROWS + o;
        se += pp[0]; so += pp[1];
    }
    if (o < 4096) {              // q: rope + fold softmax scale
        int i = (o & 127) >> 1;
        float c = fc[i], s = fs[i];
        const float SC = 0.08838834764831845f;   // 1/sqrt(128)
        g_q[m * 4096 + o]     = (se * c - so * s) * SC;
        g_q[m * 4096 + o + 1] = (se * s + so * c) * SC;
    } else if (o < 5120) {       // k: rope
        int kk = o - 4096;
        int i = (kk & 127) >> 1;
        float c = fc[i], s = fs[i];
        g_knew[m * 1024 + kk]     = se * c - so * s;
        g_knew[m * 1024 + kk + 1] = se * s + so * c;
    } else {                     // v: plain
        int vv = o - 5120;
        g_vnew[m * 1024 + vv]     = se;
        g_vnew[m * 1024 + vv + 1] = so;
    }
}

// ---------------- streaming split-softmax attention ----------------
__global__ __launch_bounds__(256) void attn_kernel(
    const float* __restrict__ cache_k, const float* __restrict__ cache_v)
{
    const int b = blockIdx.z, g = blockIdx.y, sp = blockIdx.x;
    const int warp = threadIdx.x >> 5, lane = threadIdx.x & 31;

    float4 q[4];
#pragma unroll
    for (int r = 0; r < 4; ++r)
        q[r] = *(const float4*)(g_q + ((b * NH) + g * 4 + r) * HD + lane * 4);

    float mr[4], lr[4];
    float4 acc[4];
#pragma unroll
    for (int r = 0; r < 4; ++r) {
        mr[r] = -1e30f; lr[r] = 0.f;
        acc[r] = make_float4(0.f, 0.f, 0.f, 0.f);
    }

    const int t0 = sp * 1024 + warp * 128;
#pragma unroll 4
    for (int tt = 0; tt < 128; ++tt) {
        const int t = t0 + tt;
        const size_t off = (((size_t)b * MAXSEQ + t) * NKV + g) * HD + lane * 4;
        const float* kp = cache_k + off;
        const float* vp = cache_v + off;
        if (t == NEWPOS) {
            kp = g_knew + ((b * NKV) + g) * HD + lane * 4;
            vp = g_vnew + ((b * NKV) + g) * HD + lane * 4;
        }
        const float4 kv = *(const float4*)kp;
        const float4 vv = *(const float4*)vp;

        float sc[4];
#pragma unroll
        for (int r = 0; r < 4; ++r)
            sc[r] = q[r].x * kv.x + q[r].y * kv.y + q[r].z * kv.z + q[r].w * kv.w;
#pragma unroll
        for (int r = 0; r < 4; ++r) {
            sc[r] += __shfl_xor_sync(0xffffffffu, sc[r], 16);
            sc[r] += __shfl_xor_sync(0xffffffffu, sc[r], 8);
            sc[r] += __shfl_xor_sync(0xffffffffu, sc[r], 4);
            sc[r] += __shfl_xor_sync(0xffffffffu, sc[r], 2);
            sc[r] += __shfl_xor_sync(0xffffffffu, sc[r], 1);
        }
#pragma unroll
        for (int r = 0; r < 4; ++r) {
            if (sc[r] <= mr[r]) {        // warp-uniform branch (common path: 1 exp)
                float pp = __expf(sc[r] - mr[r]);
                lr[r] += pp;
                acc[r].x += pp * vv.x; acc[r].y += pp * vv.y;
                acc[r].z += pp * vv.z; acc[r].w += pp * vv.w;
            } else {                     // new max: rescale
                float cc = __expf(mr[r] - sc[r]);
                mr[r] = sc[r];
                lr[r] = lr[r] * cc + 1.f;
                acc[r].x = acc[r].x * cc + vv.x; acc[r].y = acc[r].y * cc + vv.y;
                acc[r].z = acc[r].z * cc + vv.z; acc[r].w = acc[r].w * cc + vv.w;
            }
        }
    }

    // merge 8 warps' partial softmax states
    __shared__ float sm[8][4], sl[8][4];
    __shared__ float sacc[8][4][HD];
#pragma unroll
    for (int r = 0; r < 4; ++r) {
        *(float4*)&sacc[warp][r][lane * 4] = acc[r];
        if (lane == 0) { sm[warp][r] = mr[r]; sl[warp][r] = lr[r]; }
    }
    __syncthreads();

    const int r  = threadIdx.x / 64;
    const int j  = threadIdx.x % 64;
    const int d0 = j * 2;
    float mmax = -1e30f;
#pragma unroll
    for (int w = 0; w < 8; ++w) mmax = fmaxf(mmax, sm[w][r]);
    float L = 0.f, a0 = 0.f, a1 = 0.f;
#pragma unroll
    for (int w = 0; w < 8; ++w) {
        float e = __expf(sm[w][r] - mmax);
        L  += sl[w][r] * e;
        a0 += sacc[w][r][d0]     * e;
        a1 += sacc[w][r][d0 + 1] * e;
    }
    const int pidx = ((b * NKV + g) * ATT_SPLITS + sp) * 4 + r;
    g_pacc[(size_t)pidx * HD + d0]     = a0;
    g_pacc[(size_t)pidx * HD + d0 + 1] = a1;
    if (j == 0) { g_pm[pidx] = mmax; g_pl[pidx] = L; }
}

// ---------------- merge attention splits ----------------
__global__ void attn_combine() {
    const int bid = blockIdx.x;               // 256 = b*8 + g
    const int b = bid >> 3, g = bid & 7;
    const int tid = threadIdx.x;              // 128
    const int r = tid >> 5, lane = tid & 31, d0 = lane * 4;
    const int base = ((b * NKV + g) * ATT_SPLITS) * 4 + r;

    float mmax = -1e30f;
#pragma unroll
    for (int s = 0; s < ATT_SPLITS; ++s)
        mmax = fmaxf(mmax, g_pm[base + s * 4]);
    float L = 0.f;
    float4 a = make_float4(0.f, 0.f, 0.f, 0.f);
#pragma unroll
    for (int s = 0; s < ATT_SPLITS; ++s) {
        float e = __expf(g_pm[base + s * 4] - mmax);
        L += g_pl[base + s * 4] * e;
        const float4 pa = *(const float4*)(g_pacc + (size_t)(base + s * 4) * HD + d0);
        a.x += pa.x * e; a.y += pa.y * e; a.z += pa.z * e; a.w += pa.w * e;
    }
    const float inv = 1.f / L;
    float4 o = make_float4(a.x * inv, a.y * inv, a.z * inv, a.w * inv);
    *(float4*)(g_attn + b * 4096 + (g * 4 + r) * HD + d0) = o;
}

// ---------------- sum WO split-K partials into d_out ----------------
__global__ void o_combine(float* __restrict__ out) {
    const int i = blockIdx.x * 256 + threadIdx.x;
    if (i >= B_ * DIM_) return;
    float s = 0.f;
#pragma unroll
    for (int z = 0; z < SPLIT_O; ++z)
        s += g_part_o[(size_t)z * (B_ * DIM_) + i];
    out[i] = s;
}

// ---------------- launch ----------------
extern "C" void kernel_launch(void* const* d_in, const int* in_sizes, int n_in,
                              void* d_out, int out_size) {
    const float* x  = (const float*)d_in[0];
    // d_in[1] = start_pos (constant 4095, hardcoded)
    const float* fc = (const float*)d_in[2];
    const float* fs = (const float*)d_in[3];
    const float* ck = (const float*)d_in[4];
    const float* cv = (const float*)d_in[5];
    const float* wq = (const float*)d_in[6];
    const float* wk = (const float*)d_in[7];
    const float* wv = (const float*)d_in[8];
    const float* wo = (const float*)d_in[9];
    float* out = (float*)d_out;

    // 1) fused QKV projection (split-K f32x2 GEMM)
    gemm_splitk<<<dim3(QKV_ROWS / 128, SPLIT_QKV), 256>>>(
        x, wq, wk, wv, 4096, 5120, QKV_ROWS, SPLIT_QKV, 0);
    // 2) combine + RoPE + scatter q/k/v
    qkv_combine<<<(B_ * (QKV_ROWS / 2) + 255) / 256, 256>>>(fc, fs);
    // 3) attention over 4096 cached positions (+ new token from scratch)
    attn_kernel<<<dim3(ATT_SPLITS, NKV, B_), 256>>>(ck, cv);
    // 4) merge splits
    attn_combine<<<B_ * NKV, 128>>>();
    // 5) output projection
    gemm_splitk<<<dim3(DIM_ / 128, SPLIT_O), 256>>>(
        nullptr, wo, wo, wo, 1 << 30, 1 << 30, DIM_, SPLIT_O, 1);
    // 6) reduce into d_out
    o_combine<<<(B_ * DIM_ + 255) / 256, 256>>>(out);
}

// round 3
// speedup vs baseline: 1.2426x; 1.2426x over previous
#include <cuda_runtime.h>
#include <cstdint>
#include <cstddef>

#define B_        32
#define DIM_      4096
#define HD        128
#define NKV       8
#define NH        32
#define MAXSEQ    4096
#define NEWPOS    4095
#define QKV_ROWS  6144
#define SPLIT_QKV 6
#define SPLIT_O   9

#define T_TILE    32
#define NT        (MAXSEQ / T_TILE)     // 128 tiles
#define KROW      132                   // padded K row (floats)

typedef unsigned long long ull;

// ---------------- scratch (static __device__, no allocations) ----------------
__device__ float g_part_qkv[SPLIT_QKV * B_ * QKV_ROWS];
__device__ float g_part_o  [SPLIT_O   * B_ * DIM_];
__device__ float g_q   [B_ * NH  * HD];
__device__ float g_knew[B_ * NKV * HD];
__device__ float g_vnew[B_ * NKV * HD];
__device__ float g_attn[B_ * NH * HD];

// ---------------- f32x2 packed-FMA helpers ----------------
__device__ __forceinline__ ull splat2(float x) {
    ull r; unsigned u = __float_as_uint(x);
    asm("mov.b64 %0, {%1, %2};" : "=l"(r) : "r"(u), "r"(u));
    return r;
}
__device__ __forceinline__ ull pack2(float lo, float hi) {
    ull r;
    asm("mov.b64 %0, {%1, %2};" : "=l"(r)
        : "r"(__float_as_uint(lo)), "r"(__float_as_uint(hi)));
    return r;
}
__device__ __forceinline__ void fma2(ull& d, ull a, ull b) {
    asm("fma.rn.f32x2 %0, %1, %2, %3;" : "=l"(d) : "l"(a), "l"(b), "l"(d));
}
__device__ __forceinline__ void unpack2(ull v, float& lo, float& hi) {
    unsigned a, b;
    asm("mov.b64 {%0, %1}, %2;" : "=r"(a), "=r"(b) : "l"(v));
    lo = __uint_as_float(a); hi = __uint_as_float(b);
}

// ---------------- cp.async helpers ----------------
__device__ __forceinline__ void cp_async16(uint32_t dst, const void* src) {
    asm volatile("cp.async.cg.shared.global [%0], [%1], 16;" :: "r"(dst), "l"(src));
}
__device__ __forceinline__ void cp_commit() {
    asm volatile("cp.async.commit_group;");
}
template<int N> __device__ __forceinline__ void cp_wait() {
    asm volatile("cp.async.wait_group %0;" :: "n"(N));
}

// ---------------- split-K GEMM: C[32, Ntot] = X[32,4096] * W^T ----------------
__global__ __launch_bounds__(256) void gemm_splitk(
    const float* __restrict__ Xp,
    const float* __restrict__ W0, const float* __restrict__ W1, const float* __restrict__ W2,
    int n1, int n2, int Ntot, int nsplit, int which)
{
    __shared__ float Xs[32 * 32];
    __shared__ float Ws[32 * 128];

    const float* X    = which ? g_attn   : Xp;
    float*       part = which ? g_part_o : g_part_qkv;

    const int nb = blockIdx.x * 128;
    const int z  = blockIdx.y;
    const int kts = (z * 128) / nsplit;
    const int kte = ((z + 1) * 128) / nsplit;

    const float* W; int roff;
    if (nb < n1)      { W = W0; roff = 0;  }
    else if (nb < n2) { W = W1; roff = n1; }
    else              { W = W2; roff = n2; }

    const int t    = threadIdx.x;
    const int lane = t & 31;
    const int warp = t >> 5;
    const int m0   = warp * 4;
    const int n0   = lane * 4;

    const int lm  = t >> 3;
    const int lk4 = (t & 7) * 4;
    const float* xrow  = X + (size_t)lm * DIM_;
    const float* wbase = W + (size_t)(nb - roff) * DIM_;

    ull acc[4][2];
#pragma unroll
    for (int i = 0; i < 4; ++i) { acc[i][0] = 0ull; acc[i][1] = 0ull; }

    float4 xp4;
    float4 wp4[4];
    if (kts < kte) {
        int k0 = kts * 32;
        xp4 = *(const float4*)(xrow + k0 + lk4);
#pragma unroll
        for (int j = 0; j < 4; ++j)
            wp4[j] = *(const float4*)(wbase + (size_t)(lm + 32 * j) * DIM_ + k0 + lk4);
    }

    for (int kt = kts; kt < kte; ++kt) {
        __syncthreads();
#pragma unroll
        for (int j = 0; j < 4; ++j) {
            int kk = lk4 + j;
            int sw = ((kk >> 2) & 7) << 2;
            Xs[kk * 32 + (lm ^ sw)] = ((const float*)&xp4)[j];
        }
#pragma unroll
        for (int jj = 0; jj < 4; ++jj) {
#pragma unroll
            for (int j = 0; j < 4; ++j) {
                int kk = lk4 + j;
                int sw = ((kk >> 2) & 7) << 2;
                Ws[kk * 128 + ((lm ^ sw) + 32 * jj)] = ((const float*)&wp4[jj])[j];
            }
        }
        __syncthreads();
        if (kt + 1 < kte) {
            int k0 = (kt + 1) * 32;
            xp4 = *(const float4*)(xrow + k0 + lk4);
#pragma unroll
            for (int j = 0; j < 4; ++j)
                wp4[j] = *(const float4*)(wbase + (size_t)(lm + 32 * j) * DIM_ + k0 + lk4);
        }
#pragma unroll
        for (int kk = 0; kk < 32; ++kk) {
            int sw = ((kk >> 2) & 7) << 2;
            const float4 a4 = *(const float4*)(Xs + kk * 32  + (m0 ^ sw));
            const float4 b4 = *(const float4*)(Ws + kk * 128 + (n0 ^ sw));
            ull B0 = pack2(b4.x, b4.y);
            ull B1 = pack2(b4.z, b4.w);
            ull A;
            A = splat2(a4.x); fma2(acc[0][0], A, B0); fma2(acc[0][1], A, B1);
            A = splat2(a4.y); fma2(acc[1][0], A, B0); fma2(acc[1][1], A, B1);
            A = splat2(a4.z); fma2(acc[2][0], A, B0); fma2(acc[2][1], A, B1);
            A = splat2(a4.w); fma2(acc[3][0], A, B0); fma2(acc[3][1], A, B1);
        }
    }

    const size_t base = (size_t)z * B_ * (size_t)Ntot;
#pragma unroll
    for (int i = 0; i < 4; ++i) {
        float l0, h0, l1, h1;
        unpack2(acc[i][0], l0, h0);
        unpack2(acc[i][1], l1, h1);
        float4 o4 = make_float4(l0, h0, l1, h1);
        *(float4*)(part + base + (size_t)(m0 + i) * Ntot + nb + n0) = o4;
    }
}

// ---------------- combine QKV split-K partials + RoPE ----------------
__global__ void qkv_combine(const float* __restrict__ fc, const float* __restrict__ fs) {
    int p = blockIdx.x * blockDim.x + threadIdx.x;
    if (p >= B_ * (QKV_ROWS / 2)) return;
    int m  = p / (QKV_ROWS / 2);
    int o  = (p % (QKV_ROWS / 2)) * 2;
    float se = 0.f, so = 0.f;
#pragma unroll
    for (int z = 0; z < SPLIT_QKV; ++z) {
        const float* pp = g_part_qkv + ((size_t)z * B_ + m) * QKV_ROWS + o;
        se += pp[0]; so += pp[1];
    }
    if (o < 4096) {
        int i = (o & 127) >> 1;
        float c = fc[i], s = fs[i];
        const float SC = 0.08838834764831845f;   // 1/sqrt(128)
        g_q[m * 4096 + o]     = (se * c - so * s) * SC;
        g_q[m * 4096 + o + 1] = (se * s + so * c) * SC;
    } else if (o < 5120) {
        int kk = o - 4096;
        int i = (kk & 127) >> 1;
        float c = fc[i], s = fs[i];
        g_knew[m * 1024 + kk]     = se * c - so * s;
        g_knew[m * 1024 + kk + 1] = se * s + so * c;
    } else {
        int vv = o - 5120;
        g_vnew[m * 1024 + vv]     = se;
        g_vnew[m * 1024 + vv + 1] = so;
    }
}

// ---------------- smem-tiled, shuffle-light, branch-free decode attention -----
// One CTA per (b, g). 256 threads. 32-token tiles, double-buffered cp.async.
#define ATTN_SMEM_FLOATS (2*T_TILE*KROW + 2*T_TILE*128 + T_TILE*5 + 8)
#define ATTN_SMEM_BYTES  (ATTN_SMEM_FLOATS * 4)

__global__ __launch_bounds__(256, 2) void attn2(
    const float* __restrict__ ck, const float* __restrict__ cv)
{
    extern __shared__ float sm[];
    float* Ks      = sm;
    float* Vs      = sm + 2 * T_TILE * KROW;
    float* ss      = Vs + 2 * T_TILE * 128;
    float* scale_s = ss + T_TILE * 5;
    float* l_s     = scale_s + 4;

    const int b = blockIdx.x >> 3, g = blockIdx.x & 7;
    const int tid  = threadIdx.x;
    const int warp = tid >> 5, lane = tid & 31;

    // score mapping: 32 tokens x 4 heads x 2 half-dims
    const int t_sc = tid >> 3;
    const int r_sc = (tid >> 1) & 3;
    const int h    = tid & 1;
    // PV mapping: 4 heads x 64 dim-pairs
    const int r_pv = tid >> 6;
    const int j_pv = tid & 63;

    // q in registers: this thread's 64 dims (every other float4)
    float4 qr[16];
    const float* qbase = g_q + ((size_t)(b * NH) + g * 4 + r_sc) * HD + h * 4;
#pragma unroll
    for (int j = 0; j < 16; ++j) qr[j] = *(const float4*)(qbase + 8 * j);

    float acc0 = 0.f, acc1 = 0.f;
    float m_run = -1e30f, l_run = 0.f;   // live in warps 0..3 (replicated)

    const uint32_t ks_base = (uint32_t)__cvta_generic_to_shared(Ks);
    const uint32_t vs_base = (uint32_t)__cvta_generic_to_shared(Vs);

    const size_t kv_head_off = (size_t)g * HD;
    const size_t kv_b_off    = (size_t)b * MAXSEQ * NKV * HD;

    // issue tile 0 into buf 0
    {
#pragma unroll
        for (int c = 0; c < 4; ++c) {
            int ch = tid + c * 256;
            int row = ch >> 5, cw = ch & 31;
            size_t src = kv_b_off + (size_t)row * (NKV * HD) + kv_head_off + cw * 4;
            cp_async16(ks_base + (uint32_t)(row * KROW + cw * 4) * 4, ck + src);
            cp_async16(vs_base + (uint32_t)(row * 128  + cw * 4) * 4, cv + src);
        }
        cp_commit();
    }

    for (int i = 0; i < NT; ++i) {
        const int buf = i & 1;
        if (i + 1 < NT) {
            const int tok0 = (i + 1) * T_TILE;
            const uint32_t kdst0 = ks_base + (uint32_t)((buf ^ 1) * T_TILE * KROW) * 4;
            const uint32_t vdst0 = vs_base + (uint32_t)((buf ^ 1) * T_TILE * 128) * 4;
#pragma unroll
            for (int c = 0; c < 4; ++c) {
                int ch = tid + c * 256;
                int row = ch >> 5, cw = ch & 31;
                size_t src = kv_b_off + (size_t)(tok0 + row) * (NKV * HD) + kv_head_off + cw * 4;
                cp_async16(kdst0 + (uint32_t)(row * KROW + cw * 4) * 4, ck + src);
                cp_async16(vdst0 + (uint32_t)(row * 128  + cw * 4) * 4, cv + src);
            }
            cp_commit();
            cp_wait<1>();   // current tile done, next in flight
        } else {
            cp_wait<0>();
        }

        // patch the brand-new token (t=4095 -> tile NT-1, row 31)
        if (i == NT - 1 && tid < 64) {
            int half = tid >> 5, l2 = tid & 31;
            if (half == 0)
                *(float4*)(Ks + buf * T_TILE * KROW + 31 * KROW + l2 * 4) =
                    *(const float4*)(g_knew + (size_t)(b * NKV + g) * HD + l2 * 4);
            else
                *(float4*)(Vs + buf * T_TILE * 128 + 31 * 128 + l2 * 4) =
                    *(const float4*)(g_vnew + (size_t)(b * NKV + g) * HD + l2 * 4);
        }
        __syncthreads();

        // ---- score phase ----
        {
            const float* kb = Ks + buf * T_TILE * KROW + t_sc * KROW + h * 4;
            float s = 0.f;
#pragma unroll
            for (int j = 0; j < 16; ++j) {
                float4 kv = *(const float4*)(kb + 8 * j);
                s += qr[j].x * kv.x + qr[j].y * kv.y + qr[j].z * kv.z + qr[j].w * kv.w;
            }
            s += __shfl_xor_sync(0xffffffffu, s, 1);
            if (h == 0) ss[t_sc * 5 + r_sc] = s;
        }
        __syncthreads();

        // ---- tile softmax reduction (warps 0..3, warp == head r) ----
        if (warp < 4) {
            float sv = ss[lane * 5 + warp];
            float mx = sv;
            mx = fmaxf(mx, __shfl_xor_sync(0xffffffffu, mx, 16));
            mx = fmaxf(mx, __shfl_xor_sync(0xffffffffu, mx, 8));
            mx = fmaxf(mx, __shfl_xor_sync(0xffffffffu, mx, 4));
            mx = fmaxf(mx, __shfl_xor_sync(0xffffffffu, mx, 2));
            mx = fmaxf(mx, __shfl_xor_sync(0xffffffffu, mx, 1));
            float m_new = fmaxf(m_run, mx);
            float p = __expf(sv - m_new);
            ss[lane * 5 + warp] = p;
            float ls = p;
            ls += __shfl_xor_sync(0xffffffffu, ls, 16);
            ls += __shfl_xor_sync(0xffffffffu, ls, 8);
            ls += __shfl_xor_sync(0xffffffffu, ls, 4);
            ls += __shfl_xor_sync(0xffffffffu, ls, 2);
            ls += __shfl_xor_sync(0xffffffffu, ls, 1);
            float sc2 = __expf(m_run - m_new);
            l_run = l_run * sc2 + ls;
            m_run = m_new;
            if (lane == 0) scale_s[warp] = sc2;
        }
        __syncthreads();

        // ---- PV phase ----
        {
            float sc3 = scale_s[r_pv];
            acc0 *= sc3; acc1 *= sc3;
            const float* vb = Vs + buf * T_TILE * 128 + 2 * j_pv;
#pragma unroll
            for (int t = 0; t < T_TILE; ++t) {
                float p  = ss[t * 5 + r_pv];
                float2 vv = *(const float2*)(vb + t * 128);
                acc0 += p * vv.x;
                acc1 += p * vv.y;
            }
        }
        // next iteration's first barrier protects ss/Ks/Vs reuse
    }

    if (warp < 4 && lane == 0) l_s[warp] = l_run;
    __syncthreads();
    const float inv = 1.f / l_s[r_pv];
    float2 o = make_float2(acc0 * inv, acc1 * inv);
    *(float2*)(g_attn + (size_t)b * (NH * HD) + (g * 4 + r_pv) * HD + 2 * j_pv) = o;
}

// ---------------- sum WO split-K partials into d_out ----------------
__global__ void o_combine(float* __restrict__ out) {
    const int i = blockIdx.x * 256 + threadIdx.x;
    if (i >= B_ * DIM_) return;
    float s = 0.f;
#pragma unroll
    for (int z = 0; z < SPLIT_O; ++z)
        s += g_part_o[(size_t)z * (B_ * DIM_) + i];
    out[i] = s;
}

// ---------------- launch ----------------
extern "C" void kernel_launch(void* const* d_in, const int* in_sizes, int n_in,
                              void* d_out, int out_size) {
    const float* x  = (const float*)d_in[0];
    const float* fc = (const float*)d_in[2];
    const float* fs = (const float*)d_in[3];
    const float* ck = (const float*)d_in[4];
    const float* cv = (const float*)d_in[5];
    const float* wq = (const float*)d_in[6];
    const float* wk = (const float*)d_in[7];
    const float* wv = (const float*)d_in[8];
    const float* wo = (const float*)d_in[9];
    float* out = (float*)d_out;

    // idempotent, called every time (no static guards per harness contract)
    cudaFuncSetAttribute(attn2, cudaFuncAttributeMaxDynamicSharedMemorySize,
                         ATTN_SMEM_BYTES);

    gemm_splitk<<<dim3(QKV_ROWS / 128, SPLIT_QKV), 256>>>(
        x, wq, wk, wv, 4096, 5120, QKV_ROWS, SPLIT_QKV, 0);
    qkv_combine<<<(B_ * (QKV_ROWS / 2) + 255) / 256, 256>>>(fc, fs);
    attn2<<<B_ * NKV, 256, ATTN_SMEM_BYTES>>>(ck, cv);
    gemm_splitk<<<dim3(DIM_ / 128, SPLIT_O), 256>>>(
        nullptr, wo, wo, wo, 1 << 30, 1 << 30, DIM_, SPLIT_O, 1);
    o_combine<<<(B_ * DIM_ + 255) / 256, 256>>>(out);
}

// round 4
// speedup vs baseline: 1.4007x; 1.1272x over previous
#include <cuda_runtime.h>
#include <cstdint>
#include <cstddef>

#define B_        32
#define DIM_      4096
#define HD        128
#define NKV       8
#define NH        32
#define MAXSEQ    4096
#define QKV_ROWS  6144
#define SPLIT_QKV 6
#define SPLIT_O   9

#define T_TILE    32
#define NT        (MAXSEQ / T_TILE)     // 128 tiles
#define KROW      136                   // padded K row (conflict-free: 8t+4h banks)
#define NSTAGE    3

typedef unsigned long long ull;

// ---------------- scratch (static __device__, no allocations) ----------------
__device__ float g_part_qkv[SPLIT_QKV * B_ * QKV_ROWS];
__device__ float g_part_o  [SPLIT_O   * B_ * DIM_];
__device__ float g_q   [B_ * NH  * HD];
__device__ float g_knew[B_ * NKV * HD];
__device__ float g_vnew[B_ * NKV * HD];
__device__ float g_attn[B_ * NH * HD];

// ---------------- f32x2 packed helpers ----------------
__device__ __forceinline__ ull splat2(float x) {
    ull r; unsigned u = __float_as_uint(x);
    asm("mov.b64 %0, {%1, %2};" : "=l"(r) : "r"(u), "r"(u));
    return r;
}
__device__ __forceinline__ ull pack2(float lo, float hi) {
    ull r;
    asm("mov.b64 %0, {%1, %2};" : "=l"(r)
        : "r"(__float_as_uint(lo)), "r"(__float_as_uint(hi)));
    return r;
}
__device__ __forceinline__ void fma2(ull& d, ull a, ull b) {
    asm("fma.rn.f32x2 %0, %1, %2, %3;" : "=l"(d) : "l"(a), "l"(b), "l"(d));
}
__device__ __forceinline__ void mul2(ull& d, ull a, ull b) {
    asm("mul.rn.f32x2 %0, %1, %2;" : "=l"(d) : "l"(a), "l"(b));
}
__device__ __forceinline__ void unpack2(ull v, float& lo, float& hi) {
    unsigned a, b;
    asm("mov.b64 {%0, %1}, %2;" : "=r"(a), "=r"(b) : "l"(v));
    lo = __uint_as_float(a); hi = __uint_as_float(b);
}

// ---------------- cp.async helpers ----------------
__device__ __forceinline__ void cp_async16(uint32_t dst, const void* src) {
    asm volatile("cp.async.cg.shared.global [%0], [%1], 16;" :: "r"(dst), "l"(src));
}
__device__ __forceinline__ void cp_commit() {
    asm volatile("cp.async.commit_group;");
}
template<int N> __device__ __forceinline__ void cp_wait() {
    asm volatile("cp.async.wait_group %0;" :: "n"(N));
}

// ---------------- split-K GEMM: C[32, Ntot] = X[32,4096] * W^T ----------------
__global__ __launch_bounds__(256) void gemm_splitk(
    const float* __restrict__ Xp,
    const float* __restrict__ W0, const float* __restrict__ W1, const float* __restrict__ W2,
    int n1, int n2, int Ntot, int nsplit, int which)
{
    __shared__ float Xs[32 * 32];
    __shared__ float Ws[32 * 128];

    const float* X    = which ? g_attn   : Xp;
    float*       part = which ? g_part_o : g_part_qkv;

    const int nb = blockIdx.x * 128;
    const int z  = blockIdx.y;
    const int kts = (z * 128) / nsplit;
    const int kte = ((z + 1) * 128) / nsplit;

    const float* W; int roff;
    if (nb < n1)      { W = W0; roff = 0;  }
    else if (nb < n2) { W = W1; roff = n1; }
    else              { W = W2; roff = n2; }

    const int t    = threadIdx.x;
    const int lane = t & 31;
    const int warp = t >> 5;
    const int m0   = warp * 4;
    const int n0   = lane * 4;

    const int lm  = t >> 3;
    const int lk4 = (t & 7) * 4;
    const float* xrow  = X + (size_t)lm * DIM_;
    const float* wbase = W + (size_t)(nb - roff) * DIM_;

    ull acc[4][2];
#pragma unroll
    for (int i = 0; i < 4; ++i) { acc[i][0] = 0ull; acc[i][1] = 0ull; }

    float4 xp4;
    float4 wp4[4];
    if (kts < kte) {
        int k0 = kts * 32;
        xp4 = *(const float4*)(xrow + k0 + lk4);
#pragma unroll
        for (int j = 0; j < 4; ++j)
            wp4[j] = *(const float4*)(wbase + (size_t)(lm + 32 * j) * DIM_ + k0 + lk4);
    }

    for (int kt = kts; kt < kte; ++kt) {
        __syncthreads();
#pragma unroll
        for (int j = 0; j < 4; ++j) {
            int kk = lk4 + j;
            int sw = ((kk >> 2) & 7) << 2;
            Xs[kk * 32 + (lm ^ sw)] = ((const float*)&xp4)[j];
        }
#pragma unroll
        for (int jj = 0; jj < 4; ++jj) {
#pragma unroll
            for (int j = 0; j < 4; ++j) {
                int kk = lk4 + j;
                int sw = ((kk >> 2) & 7) << 2;
                Ws[kk * 128 + ((lm ^ sw) + 32 * jj)] = ((const float*)&wp4[jj])[j];
            }
        }
        __syncthreads();
        if (kt + 1 < kte) {
            int k0 = (kt + 1) * 32;
            xp4 = *(const float4*)(xrow + k0 + lk4);
#pragma unroll
            for (int j = 0; j < 4; ++j)
                wp4[j] = *(const float4*)(wbase + (size_t)(lm + 32 * j) * DIM_ + k0 + lk4);
        }
#pragma unroll
        for (int kk = 0; kk < 32; ++kk) {
            int sw = ((kk >> 2) & 7) << 2;
            const float4 a4 = *(const float4*)(Xs + kk * 32  + (m0 ^ sw));
            const float4 b4 = *(const float4*)(Ws + kk * 128 + (n0 ^ sw));
            ull B0 = pack2(b4.x, b4.y);
            ull B1 = pack2(b4.z, b4.w);
            ull A;
            A = splat2(a4.x); fma2(acc[0][0], A, B0); fma2(acc[0][1], A, B1);
            A = splat2(a4.y); fma2(acc[1][0], A, B0); fma2(acc[1][1], A, B1);
            A = splat2(a4.z); fma2(acc[2][0], A, B0); fma2(acc[2][1], A, B1);
            A = splat2(a4.w); fma2(acc[3][0], A, B0); fma2(acc[3][1], A, B1);
        }
    }

    const size_t base = (size_t)z * B_ * (size_t)Ntot;
#pragma unroll
    for (int i = 0; i < 4; ++i) {
        float l0, h0, l1, h1;
        unpack2(acc[i][0], l0, h0);
        unpack2(acc[i][1], l1, h1);
        float4 o4 = make_float4(l0, h0, l1, h1);
        *(float4*)(part + base + (size_t)(m0 + i) * Ntot + nb + n0) = o4;
    }
}

// ---------------- combine QKV split-K partials + RoPE ----------------
__global__ void qkv_combine(const float* __restrict__ fc, const float* __restrict__ fs) {
    int p = blockIdx.x * blockDim.x + threadIdx.x;
    if (p >= B_ * (QKV_ROWS / 2)) return;
    int m  = p / (QKV_ROWS / 2);
    int o  = (p % (QKV_ROWS / 2)) * 2;
    float se = 0.f, so = 0.f;
#pragma unroll
    for (int z = 0; z < SPLIT_QKV; ++z) {
        const float* pp = g_part_qkv + ((size_t)z * B_ + m) * QKV_ROWS + o;
        se += pp[0]; so += pp[1];
    }
    if (o < 4096) {
        int i = (o & 127) >> 1;
        float c = fc[i], s = fs[i];
        const float SC = 0.08838834764831845f;   // 1/sqrt(128)
        g_q[m * 4096 + o]     = (se * c - so * s) * SC;
        g_q[m * 4096 + o + 1] = (se * s + so * c) * SC;
    } else if (o < 5120) {
        int kk = o - 4096;
        int i = (kk & 127) >> 1;
        float c = fc[i], s = fs[i];
        g_knew[m * 1024 + kk]     = se * c - so * s;
        g_knew[m * 1024 + kk + 1] = se * s + so * c;
    } else {
        int vv = o - 5120;
        g_vnew[m * 1024 + vv]     = se;
        g_vnew[m * 1024 + vv + 1] = so;
    }
}

// ---------------- 3-stage pipelined, f32x2, conflict-free decode attention ----
// One CTA per (b, g). 256 threads. 32-token tiles.
// Smem (floats): Ks 3*32*136 | Vs 3*32*128 | pr 4*34 | scale 4 | l 4
#define KS_FLOATS (NSTAGE * T_TILE * KROW)
#define VS_FLOATS (NSTAGE * T_TILE * 128)
#define ATTN_SMEM_FLOATS (KS_FLOATS + VS_FLOATS + 4*34 + 8)
#define ATTN_SMEM_BYTES  (ATTN_SMEM_FLOATS * 4)

__global__ __launch_bounds__(256, 2) void attn3(
    const float* __restrict__ ck, const float* __restrict__ cv)
{
    extern __shared__ float sm[];
    float* Ks      = sm;
    float* Vs      = sm + KS_FLOATS;
    float* pr      = Vs + VS_FLOATS;
    float* scale_s = pr + 4 * 34;
    float* l_s     = scale_s + 4;

    const int b = blockIdx.x >> 3, g = blockIdx.x & 7;
    const int tid  = threadIdx.x;
    const int warp = tid >> 5, lane = tid & 31;

    // score mapping: 32 tokens x 4 heads x 2 half-dims
    const int t_sc = tid >> 3;
    const int r_sc = (tid >> 1) & 3;
    const int h    = tid & 1;
    // PV mapping: 4 heads x 64 dim-pairs
    const int r_pv = tid >> 6;
    const int j_pv = tid & 63;

    // q (this thread's 64 dims: h*4 + 8j + 0..3) as 32 packed f32x2
    ull qu[32];
    {
        const float* qbase = g_q + ((size_t)(b * NH) + g * 4 + r_sc) * HD + h * 4;
#pragma unroll
        for (int j = 0; j < 16; ++j) {
            ulonglong2 t2 = *(const ulonglong2*)(qbase + 8 * j);
            qu[2 * j]     = t2.x;
            qu[2 * j + 1] = t2.y;
        }
    }

    ull accp = 0ull;                      // packed (dim 2j_pv, 2j_pv+1)
    float m_run = -1e30f, l_run = 0.f;    // live in warps 0..3

    const uint32_t ks_base = (uint32_t)__cvta_generic_to_shared(Ks);
    const uint32_t vs_base = (uint32_t)__cvta_generic_to_shared(Vs);

    const size_t kv_head_off = (size_t)g * HD;
    const size_t kv_b_off    = (size_t)b * MAXSEQ * NKV * HD;

    const int row_l = tid >> 5;           // loader row base (8 rows/pass)
    const int cw    = tid & 31;           // 4-float chunk within row

    // preload tiles 0,1 into stages 0,1 (one commit group each)
#pragma unroll
    for (int pre = 0; pre < 2; ++pre) {
        const uint32_t kd = ks_base + (uint32_t)(pre * T_TILE * KROW) * 4;
        const uint32_t vd = vs_base + (uint32_t)(pre * T_TILE * 128) * 4;
#pragma unroll
        for (int c = 0; c < 4; ++c) {
            int row = row_l + c * 8;
            size_t src = kv_b_off + (size_t)(pre * T_TILE + row) * (NKV * HD) + kv_head_off + cw * 4;
            cp_async16(kd + (uint32_t)(row * KROW + cw * 4) * 4, ck + src);
            cp_async16(vd + (uint32_t)(row * 128  + cw * 4) * 4, cv + src);
        }
        cp_commit();
    }

    for (int i = 0; i < NT; ++i) {
        const int buf = i % NSTAGE;

        __syncthreads();   // closes PV(i-1): safe to overwrite stage (i+2)%3 == (i-1)%3

        if (i + 2 < NT) {
            const int st = (i + 2) % NSTAGE;
            const int tok0 = (i + 2) * T_TILE;
            const uint32_t kd = ks_base + (uint32_t)(st * T_TILE * KROW) * 4;
            const uint32_t vd = vs_base + (uint32_t)(st * T_TILE * 128) * 4;
#pragma unroll
            for (int c = 0; c < 4; ++c) {
                int row = row_l + c * 8;
                size_t src = kv_b_off + (size_t)(tok0 + row) * (NKV * HD) + kv_head_off + cw * 4;
                cp_async16(kd + (uint32_t)(row * KROW + cw * 4) * 4, ck + src);
                cp_async16(vd + (uint32_t)(row * 128  + cw * 4) * 4, cv + src);
            }
            cp_commit();
            cp_wait<2>();          // tile i complete (2 newer groups pending)
        } else if (i + 1 < NT) {
            cp_wait<1>();
        } else {
            cp_wait<0>();
        }

        // patch the brand-new token (t=4095 -> last tile, row 31) after data landed
        if (i == NT - 1 && tid < 64) {
            int half = tid >> 5, l2 = tid & 31;
            if (half == 0)
                *(float4*)(Ks + buf * T_TILE * KROW + 31 * KROW + l2 * 4) =
                    *(const float4*)(g_knew + (size_t)(b * NKV + g) * HD + l2 * 4);
            else
                *(float4*)(Vs + buf * T_TILE * 128 + 31 * 128 + l2 * 4) =
                    *(const float4*)(g_vnew + (size_t)(b * NKV + g) * HD + l2 * 4);
        }
        __syncthreads();

        // ---- score phase: packed dot over this thread's 64 dims ----
        {
            const float* kb = Ks + buf * T_TILE * KROW + t_sc * KROW + h * 4;
            ull a0 = 0ull, a1 = 0ull;
#pragma unroll
            for (int j = 0; j < 16; ++j) {
                ulonglong2 kv = *(const ulonglong2*)(kb + 8 * j);
                fma2(a0, qu[2 * j],     kv.x);
                fma2(a1, qu[2 * j + 1], kv.y);
            }
            float x0, x1, x2, x3;
            unpack2(a0, x0, x1);
            unpack2(a1, x2, x3);
            float s = (x0 + x1) + (x2 + x3);
            s += __shfl_xor_sync(0xffffffffu, s, 1);
            if (h == 0) pr[r_sc * 34 + t_sc] = s;
        }
        __syncthreads();

        // ---- tile softmax (warps 0..3; warp == head) ----
        if (warp < 4) {
            float sv = pr[warp * 34 + lane];
            float mx = sv;
            mx = fmaxf(mx, __shfl_xor_sync(0xffffffffu, mx, 16));
            mx = fmaxf(mx, __shfl_xor_sync(0xffffffffu, mx, 8));
            mx = fmaxf(mx, __shfl_xor_sync(0xffffffffu, mx, 4));
            mx = fmaxf(mx, __shfl_xor_sync(0xffffffffu, mx, 2));
            mx = fmaxf(mx, __shfl_xor_sync(0xffffffffu, mx, 1));
            float m_new = fmaxf(m_run, mx);
            float p = __expf(sv - m_new);
            pr[warp * 34 + lane] = p;
            float ls = p;
            ls += __shfl_xor_sync(0xffffffffu, ls, 16);
            ls += __shfl_xor_sync(0xffffffffu, ls, 8);
            ls += __shfl_xor_sync(0xffffffffu, ls, 4);
            ls += __shfl_xor_sync(0xffffffffu, ls, 2);
            ls += __shfl_xor_sync(0xffffffffu, ls, 1);
            float sc2 = __expf(m_run - m_new);
            l_run = l_run * sc2 + ls;
            m_run = m_new;
            if (lane == 0) scale_s[warp] = sc2;
        }
        __syncthreads();

        // ---- PV phase: 2 tokens/iter, packed fma ----
        {
            ull s2 = splat2(scale_s[r_pv]);
            mul2(accp, accp, s2);
            const float* vb = Vs + buf * T_TILE * 128 + 2 * j_pv;
            const float* pb = pr + r_pv * 34;
#pragma unroll
            for (int t2 = 0; t2 < T_TILE / 2; ++t2) {
                float2 p2 = *(const float2*)(pb + 2 * t2);
                ull v0 = *(const ull*)(vb + (2 * t2) * 128);
                ull v1 = *(const ull*)(vb + (2 * t2 + 1) * 128);
                fma2(accp, splat2(p2.x), v0);
                fma2(accp, splat2(p2.y), v1);
            }
        }
    }

    if (warp < 4 && lane == 0) l_s[warp] = l_run;
    __syncthreads();
    const float inv = 1.f / l_s[r_pv];
    float a0, a1;
    unpack2(accp, a0, a1);
    float2 o = make_float2(a0 * inv, a1 * inv);
    *(float2*)(g_attn + (size_t)b * (NH * HD) + (g * 4 + r_pv) * HD + 2 * j_pv) = o;
}

// ---------------- sum WO split-K partials into d_out ----------------
__global__ void o_combine(float* __restrict__ out) {
    const int i = blockIdx.x * 256 + threadIdx.x;
    if (i >= B_ * DIM_) return;
    float s = 0.f;
#pragma unroll
    for (int z = 0; z < SPLIT_O; ++z)
        s += g_part_o[(size_t)z * (B_ * DIM_) + i];
    out[i] = s;
}

// ---------------- launch ----------------
extern "C" void kernel_launch(void* const* d_in, const int* in_sizes, int n_in,
                              void* d_out, int out_size) {
    const float* x  = (const float*)d_in[0];
    const float* fc = (const float*)d_in[2];
    const float* fs = (const float*)d_in[3];
    const float* ck = (const float*)d_in[4];
    const float* cv = (const float*)d_in[5];
    const float* wq = (const float*)d_in[6];
    const float* wk = (const float*)d_in[7];
    const float* wv = (const float*)d_in[8];
    const float* wo = (const float*)d_in[9];
    float* out = (float*)d_out;

    cudaFuncSetAttribute(attn3, cudaFuncAttributeMaxDynamicSharedMemorySize,
                         ATTN_SMEM_BYTES);

    gemm_splitk<<<dim3(QKV_ROWS / 128, SPLIT_QKV), 256>>>(
        x, wq, wk, wv, 4096, 5120, QKV_ROWS, SPLIT_QKV, 0);
    qkv_combine<<<(B_ * (QKV_ROWS / 2) + 255) / 256, 256>>>(fc, fs);
    attn3<<<B_ * NKV, 256, ATTN_SMEM_BYTES>>>(ck, cv);
    gemm_splitk<<<dim3(DIM_ / 128, SPLIT_O), 256>>>(
        nullptr, wo, wo, wo, 1 << 30, 1 << 30, DIM_, SPLIT_O, 1);
    o_combine<<<(B_ * DIM_ + 255) / 256, 256>>>(out);
}

// round 7
// speedup vs baseline: 1.4515x; 1.0363x over previous
#include <cuda_runtime.h>
#include <cstdint>
#include <cstddef>

#define B_        32
#define DIM_      4096
#define HD        128
#define NKV       8
#define NH        32
#define MAXSEQ    4096
#define QKV_ROWS  6144
#define SPLIT_QKV 12
#define SPLIT_O   18
#define ATT_SPLITS 8
#define TOK_PER_SPLIT (MAXSEQ / ATT_SPLITS)   // 512

#define T_TILE    32
#define NT_LOC    (TOK_PER_SPLIT / T_TILE)    // 16 tiles per CTA
#define KROW      136                          // padded K row
#define NSTAGE    3

typedef unsigned long long ull;

// ---------------- scratch (static __device__, no allocations) ----------------
__device__ float g_part_qkv[SPLIT_QKV * B_ * QKV_ROWS];
__device__ float g_part_o  [SPLIT_O   * B_ * DIM_];
__device__ float g_q   [B_ * NH  * HD];
__device__ float g_knew[B_ * NKV * HD];
__device__ float g_vnew[B_ * NKV * HD];
__device__ float g_attn[B_ * NH * HD];
__device__ float g_pacc[B_ * NKV * ATT_SPLITS * 4 * HD];
__device__ float g_pm  [B_ * NKV * ATT_SPLITS * 4];
__device__ float g_pl  [B_ * NKV * ATT_SPLITS * 4];

// ---------------- f32x2 packed helpers ----------------
__device__ __forceinline__ ull splat2(float x) {
    ull r; unsigned u = __float_as_uint(x);
    asm("mov.b64 %0, {%1, %2};" : "=l"(r) : "r"(u), "r"(u));
    return r;
}
__device__ __forceinline__ ull pack2(float lo, float hi) {
    ull r;
    asm("mov.b64 %0, {%1, %2};" : "=l"(r)
        : "r"(__float_as_uint(lo)), "r"(__float_as_uint(hi)));
    return r;
}
__device__ __forceinline__ void fma2(ull& d, ull a, ull b) {
    asm("fma.rn.f32x2 %0, %1, %2, %3;" : "=l"(d) : "l"(a), "l"(b), "l"(d));
}
__device__ __forceinline__ void mul2(ull& d, ull a, ull b) {
    asm("mul.rn.f32x2 %0, %1, %2;" : "=l"(d) : "l"(a), "l"(b));
}
__device__ __forceinline__ void unpack2(ull v, float& lo, float& hi) {
    unsigned a, b;
    asm("mov.b64 {%0, %1}, %2;" : "=r"(a), "=r"(b) : "l"(v));
    lo = __uint_as_float(a); hi = __uint_as_float(b);
}

// ---------------- cp.async helpers ----------------
__device__ __forceinline__ void cp_async16(uint32_t dst, const void* src) {
    asm volatile("cp.async.cg.shared.global [%0], [%1], 16;" :: "r"(dst), "l"(src));
}
__device__ __forceinline__ void cp_commit() {
    asm volatile("cp.async.commit_group;");
}
template<int N> __device__ __forceinline__ void cp_wait() {
    asm volatile("cp.async.wait_group %0;" :: "n"(N));
}

// ---------------- split-K GEMM: C[32, Ntot] = X[32,4096] * W^T ----------------
__global__ __launch_bounds__(256) void gemm_splitk(
    const float* __restrict__ Xp,
    const float* __restrict__ W0, const float* __restrict__ W1, const float* __restrict__ W2,
    int n1, int n2, int Ntot, int nsplit, int which)
{
    __shared__ float Xs[32 * 32];
    __shared__ float Ws[32 * 128];

    const float* X    = which ? g_attn   : Xp;
    float*       part = which ? g_part_o : g_part_qkv;

    const int nb = blockIdx.x * 128;
    const int z  = blockIdx.y;
    const int kts = (z * 128) / nsplit;
    const int kte = ((z + 1) * 128) / nsplit;

    const float* W; int roff;
    if (nb < n1)      { W = W0; roff = 0;  }
    else if (nb < n2) { W = W1; roff = n1; }
    else              { W = W2; roff = n2; }

    const int t    = threadIdx.x;
    const int lane = t & 31;
    const int warp = t >> 5;
    const int m0   = warp * 4;
    const int n0   = lane * 4;

    const int lm  = t >> 3;
    const int lk4 = (t & 7) * 4;
    const float* xrow  = X + (size_t)lm * DIM_;
    const float* wbase = W + (size_t)(nb - roff) * DIM_;

    ull acc[4][2];
#pragma unroll
    for (int i = 0; i < 4; ++i) { acc[i][0] = 0ull; acc[i][1] = 0ull; }

    float4 xp4;
    float4 wp4[4];
    if (kts < kte) {
        int k0 = kts * 32;
        xp4 = *(const float4*)(xrow + k0 + lk4);
#pragma unroll
        for (int j = 0; j < 4; ++j)
            wp4[j] = *(const float4*)(wbase + (size_t)(lm + 32 * j) * DIM_ + k0 + lk4);
    }

    for (int kt = kts; kt < kte; ++kt) {
        __syncthreads();
#pragma unroll
        for (int j = 0; j < 4; ++j) {
            int kk = lk4 + j;
            int sw = ((kk >> 2) & 7) << 2;
            Xs[kk * 32 + (lm ^ sw)] = ((const float*)&xp4)[j];
        }
#pragma unroll
        for (int jj = 0; jj < 4; ++jj) {
#pragma unroll
            for (int j = 0; j < 4; ++j) {
                int kk = lk4 + j;
                int sw = ((kk >> 2) & 7) << 2;
                Ws[kk * 128 + ((lm ^ sw) + 32 * jj)] = ((const float*)&wp4[jj])[j];
            }
        }
        __syncthreads();
        if (kt + 1 < kte) {
            int k0 = (kt + 1) * 32;
            xp4 = *(const float4*)(xrow + k0 + lk4);
#pragma unroll
            for (int j = 0; j < 4; ++j)
                wp4[j] = *(const float4*)(wbase + (size_t)(lm + 32 * j) * DIM_ + k0 + lk4);
        }
#pragma unroll
        for (int kk = 0; kk < 32; ++kk) {
            int sw = ((kk >> 2) & 7) << 2;
            const float4 a4 = *(const float4*)(Xs + kk * 32  + (m0 ^ sw));
            const float4 b4 = *(const float4*)(Ws + kk * 128 + (n0 ^ sw));
            ull B0 = pack2(b4.x, b4.y);
            ull B1 = pack2(b4.z, b4.w);
            ull A;
            A = splat2(a4.x); fma2(acc[0][0], A, B0); fma2(acc[0][1], A, B1);
            A = splat2(a4.y); fma2(acc[1][0], A, B0); fma2(acc[1][1], A, B1);
            A = splat2(a4.z); fma2(acc[2][0], A, B0); fma2(acc[2][1], A, B1);
            A = splat2(a4.w); fma2(acc[3][0], A, B0); fma2(acc[3][1], A, B1);
        }
    }

    const size_t base = (size_t)z * B_ * (size_t)Ntot;
#pragma unroll
    for (int i = 0; i < 4; ++i) {
        float l0, h0, l1, h1;
        unpack2(acc[i][0], l0, h0);
        unpack2(acc[i][1], l1, h1);
        float4 o4 = make_float4(l0, h0, l1, h1);
        *(float4*)(part + base + (size_t)(m0 + i) * Ntot + nb + n0) = o4;
    }
}

// ---------------- combine QKV split-K partials + RoPE ----------------
__global__ void qkv_combine(const float* __restrict__ fc, const float* __restrict__ fs) {
    int p = blockIdx.x * blockDim.x + threadIdx.x;
    if (p >= B_ * (QKV_ROWS / 2)) return;
    int m  = p / (QKV_ROWS / 2);
    int o  = (p % (QKV_ROWS / 2)) * 2;
    float se = 0.f, so = 0.f;
#pragma unroll
    for (int z = 0; z < SPLIT_QKV; ++z) {
        const float* pp = g_part_qkv + ((size_t)z * B_ + m) * QKV_ROWS + o;
        se += pp[0]; so += pp[1];
    }
    if (o < 4096) {
        int i = (o & 127) >> 1;
        float c = fc[i], s = fs[i];
        const float SC = 0.08838834764831845f;   // 1/sqrt(128)
        g_q[m * 4096 + o]     = (se * c - so * s) * SC;
        g_q[m * 4096 + o + 1] = (se * s + so * c) * SC;
    } else if (o < 5120) {
        int kk = o - 4096;
        int i = (kk & 127) >> 1;
        float c = fc[i], s = fs[i];
        g_knew[m * 1024 + kk]     = se * c - so * s;
        g_knew[m * 1024 + kk + 1] = se * s + so * c;
    } else {
        int vv = o - 5120;
        g_vnew[m * 1024 + vv]     = se;
        g_vnew[m * 1024 + vv + 1] = so;
    }
}

// ---------------- 3-stage pipelined, f32x2, split-softmax decode attention ----
// Grid (ATT_SPLITS, NKV, B_). One CTA per (b, g, split). 256 threads.
#define KS_FLOATS (NSTAGE * T_TILE * KROW)
#define VS_FLOATS (NSTAGE * T_TILE * 128)
#define ATTN_SMEM_FLOATS (KS_FLOATS + VS_FLOATS + 4*34 + 8)
#define ATTN_SMEM_BYTES  (ATTN_SMEM_FLOATS * 4)

__global__ __launch_bounds__(256, 2) void attn3(
    const float* __restrict__ ck, const float* __restrict__ cv)
{
    extern __shared__ float sm[];
    float* Ks      = sm;
    float* Vs      = sm + KS_FLOATS;
    float* pr      = Vs + VS_FLOATS;
    float* scale_s = pr + 4 * 34;

    const int sp = blockIdx.x, g = blockIdx.y, b = blockIdx.z;
    const int tid  = threadIdx.x;
    const int warp = tid >> 5, lane = tid & 31;

    // score mapping: 32 tokens x 4 heads x 2 half-dims
    const int t_sc = tid >> 3;
    const int r_sc = (tid >> 1) & 3;
    const int h    = tid & 1;
    // PV mapping: 4 heads x 64 dim-pairs
    const int r_pv = tid >> 6;
    const int j_pv = tid & 63;

    // q (this thread's 64 dims) as 32 packed f32x2
    ull qu[32];
    {
        const float* qbase = g_q + ((size_t)(b * NH) + g * 4 + r_sc) * HD + h * 4;
#pragma unroll
        for (int j = 0; j < 16; ++j) {
            ulonglong2 t2 = *(const ulonglong2*)(qbase + 8 * j);
            qu[2 * j]     = t2.x;
            qu[2 * j + 1] = t2.y;
        }
    }

    ull accp = 0ull;
    float m_run = -1e30f, l_run = 0.f;

    const uint32_t ks_base = (uint32_t)__cvta_generic_to_shared(Ks);
    const uint32_t vs_base = (uint32_t)__cvta_generic_to_shared(Vs);

    const size_t kv_head_off = (size_t)g * HD;
    const size_t kv_b_off = (size_t)b * MAXSEQ * NKV * HD
                          + (size_t)sp * TOK_PER_SPLIT * NKV * HD;

    const int row_l = tid >> 5;
    const int cw    = tid & 31;

    // preload tiles 0,1 into stages 0,1
#pragma unroll
    for (int pre = 0; pre < 2; ++pre) {
        const uint32_t kd = ks_base + (uint32_t)(pre * T_TILE * KROW) * 4;
        const uint32_t vd = vs_base + (uint32_t)(pre * T_TILE * 128) * 4;
#pragma unroll
        for (int c = 0; c < 4; ++c) {
            int row = row_l + c * 8;
            size_t src = kv_b_off + (size_t)(pre * T_TILE + row) * (NKV * HD) + kv_head_off + cw * 4;
            cp_async16(kd + (uint32_t)(row * KROW + cw * 4) * 4, ck + src);
            cp_async16(vd + (uint32_t)(row * 128  + cw * 4) * 4, cv + src);
        }
        cp_commit();
    }

    for (int i = 0; i < NT_LOC; ++i) {
        const int buf = i % NSTAGE;

        __syncthreads();   // closes PV(i-1): stage being overwritten is free

        if (i + 2 < NT_LOC) {
            const int st = (i + 2) % NSTAGE;
            const int tok0 = (i + 2) * T_TILE;
            const uint32_t kd = ks_base + (uint32_t)(st * T_TILE * KROW) * 4;
            const uint32_t vd = vs_base + (uint32_t)(st * T_TILE * 128) * 4;
#pragma unroll
            for (int c = 0; c < 4; ++c) {
                int row = row_l + c * 8;
                size_t src = kv_b_off + (size_t)(tok0 + row) * (NKV * HD) + kv_head_off + cw * 4;
                cp_async16(kd + (uint32_t)(row * KROW + cw * 4) * 4, ck + src);
                cp_async16(vd + (uint32_t)(row * 128  + cw * 4) * 4, cv + src);
            }
            cp_commit();
            cp_wait<2>();
        } else if (i + 1 < NT_LOC) {
            cp_wait<1>();
        } else {
            cp_wait<0>();
        }

        // patch new token (t=4095 -> last split, last tile, row 31)
        if (sp == ATT_SPLITS - 1 && i == NT_LOC - 1 && tid < 64) {
            int half = tid >> 5, l2 = tid & 31;
            if (half == 0)
                *(float4*)(Ks + buf * T_TILE * KROW + 31 * KROW + l2 * 4) =
                    *(const float4*)(g_knew + (size_t)(b * NKV + g) * HD + l2 * 4);
            else
                *(float4*)(Vs + buf * T_TILE * 128 + 31 * 128 + l2 * 4) =
                    *(const float4*)(g_vnew + (size_t)(b * NKV + g) * HD + l2 * 4);
        }
        __syncthreads();

        // ---- score phase ----
        {
            const float* kb = Ks + buf * T_TILE * KROW + t_sc * KROW + h * 4;
            ull a0 = 0ull, a1 = 0ull;
#pragma unroll
            for (int j = 0; j < 16; ++j) {
                ulonglong2 kv = *(const ulonglong2*)(kb + 8 * j);
                fma2(a0, qu[2 * j],     kv.x);
                fma2(a1, qu[2 * j + 1], kv.y);
            }
            float x0, x1, x2, x3;
            unpack2(a0, x0, x1);
            unpack2(a1, x2, x3);
            float s = (x0 + x1) + (x2 + x3);
            s += __shfl_xor_sync(0xffffffffu, s, 1);
            if (h == 0) pr[r_sc * 34 + t_sc] = s;
        }
        __syncthreads();

        // ---- tile softmax (warps 0..3; warp == head) ----
        if (warp < 4) {
            float sv = pr[warp * 34 + lane];
            float mx = sv;
            mx = fmaxf(mx, __shfl_xor_sync(0xffffffffu, mx, 16));
            mx = fmaxf(mx, __shfl_xor_sync(0xffffffffu, mx, 8));
            mx = fmaxf(mx, __shfl_xor_sync(0xffffffffu, mx, 4));
            mx = fmaxf(mx, __shfl_xor_sync(0xffffffffu, mx, 2));
            mx = fmaxf(mx, __shfl_xor_sync(0xffffffffu, mx, 1));
            float m_new = fmaxf(m_run, mx);
            float p = __expf(sv - m_new);
            pr[warp * 34 + lane] = p;
            float ls = p;
            ls += __shfl_xor_sync(0xffffffffu, ls, 16);
            ls += __shfl_xor_sync(0xffffffffu, ls, 8);
            ls += __shfl_xor_sync(0xffffffffu, ls, 4);
            ls += __shfl_xor_sync(0xffffffffu, ls, 2);
            ls += __shfl_xor_sync(0xffffffffu, ls, 1);
            float sc2 = __expf(m_run - m_new);
            l_run = l_run * sc2 + ls;
            m_run = m_new;
            if (lane == 0) scale_s[warp] = sc2;
        }
        __syncthreads();

        // ---- PV phase: 2 tokens/iter, packed fma ----
        {
            ull s2 = splat2(scale_s[r_pv]);
            mul2(accp, accp, s2);
            const float* vb = Vs + buf * T_TILE * 128 + 2 * j_pv;
            const float* pb = pr + r_pv * 34;
#pragma unroll
            for (int t2 = 0; t2 < T_TILE / 2; ++t2) {
                float2 p2 = *(const float2*)(pb + 2 * t2);
                ull v0 = *(const ull*)(vb + (2 * t2) * 128);
                ull v1 = *(const ull*)(vb + (2 * t2 + 1) * 128);
                fma2(accp, splat2(p2.x), v0);
                fma2(accp, splat2(p2.y), v1);
            }
        }
    }

    // write split partials (unnormalized)
    if (warp < 4 && lane == 0) {
        const int pidx = ((b * NKV + g) * ATT_SPLITS + sp) * 4 + warp;
        g_pm[pidx] = m_run;
        g_pl[pidx] = l_run;
    }
    {
        const int pidx = ((b * NKV + g) * ATT_SPLITS + sp) * 4 + r_pv;
        float a0, a1;
        unpack2(accp, a0, a1);
        *(float2*)(g_pacc + (size_t)pidx * HD + 2 * j_pv) = make_float2(a0, a1);
    }
}

// ---------------- merge attention splits ----------------
__global__ void attn_combine() {
    const int bid = blockIdx.x;               // 256 = b*8 + g
    const int b = bid >> 3, g = bid & 7;
    const int tid = threadIdx.x;              // 128
    const int r = tid >> 5, lane = tid & 31, d0 = lane * 4;
    const int base = ((b * NKV + g) * ATT_SPLITS) * 4 + r;

    float mmax = -1e30f;
#pragma unroll
    for (int s = 0; s < ATT_SPLITS; ++s)
        mmax = fmaxf(mmax, g_pm[base + s * 4]);
    float L = 0.f;
    float4 a = make_float4(0.f, 0.f, 0.f, 0.f);
#pragma unroll
    for (int s = 0; s < ATT_SPLITS; ++s) {
        float e = __expf(g_pm[base + s * 4] - mmax);
        L += g_pl[base + s * 4] * e;
        const float4 pa = *(const float4*)(g_pacc + (size_t)(base + s * 4) * HD + d0);
        a.x += pa.x * e; a.y += pa.y * e; a.z += pa.z * e; a.w += pa.w * e;
    }
    const float inv = 1.f / L;
    float4 o = make_float4(a.x * inv, a.y * inv, a.z * inv, a.w * inv);
    *(float4*)(g_attn + (size_t)b * 4096 + (g * 4 + r) * HD + d0) = o;
}

// ---------------- sum WO split-K partials into d_out ----------------
__global__ void o_combine(float* __restrict__ out) {
    const int i = blockIdx.x * 256 + threadIdx.x;
    if (i >= B_ * DIM_) return;
    float s = 0.f;
#pragma unroll
    for (int z = 0; z < SPLIT_O; ++z)
        s += g_part_o[(size_t)z * (B_ * DIM_) + i];
    out[i] = s;
}

// ---------------- launch ----------------
extern "C" void kernel_launch(void* const* d_in, const int* in_sizes, int n_in,
                              void* d_out, int out_size) {
    const float* x  = (const float*)d_in[0];
    const float* fc = (const float*)d_in[2];
    const float* fs = (const float*)d_in[3];
    const float* ck = (const float*)d_in[4];
    const float* cv = (const float*)d_in[5];
    const float* wq = (const float*)d_in[6];
    const float* wk = (const float*)d_in[7];
    const float* wv = (const float*)d_in[8];
    const float* wo = (const float*)d_in[9];
    float* out = (float*)d_out;

    cudaFuncSetAttribute(attn3, cudaFuncAttributeMaxDynamicSharedMemorySize,
                         ATTN_SMEM_BYTES);

    gemm_splitk<<<dim3(QKV_ROWS / 128, SPLIT_QKV), 256>>>(
        x, wq, wk, wv, 4096, 5120, QKV_ROWS, SPLIT_QKV, 0);
    qkv_combine<<<(B_ * (QKV_ROWS / 2) + 255) / 256, 256>>>(fc, fs);
    attn3<<<dim3(ATT_SPLITS, NKV, B_), 256, ATTN_SMEM_BYTES>>>(ck, cv);
    attn_combine<<<B_ * NKV, 128>>>();
    gemm_splitk<<<dim3(DIM_ / 128, SPLIT_O), 256>>>(
        nullptr, wo, wo, wo, 1 << 30, 1 << 30, DIM_, SPLIT_O, 1);
    o_combine<<<(B_ * DIM_ + 255) / 256, 256>>>(out);
}